// round 5
// baseline (speedup 1.0000x reference)
#include <cuda_runtime.h>
#include <cstdint>

// Problem constants
#define B_TOT   256
#define IN_CAPS 3200
#define NJ      8
#define NM      16
#define NN      8
#define JM      (NJ * NM)          // 128

// Tiling
#define IC      32                 // input caps per chunk
#define NCHUNK  (IN_CAPS / IC)     // 100
#define BPC     32                 // batch elems per CTA (16 warps x 2)
#define NBB     (B_TOT / BPC)      // 8
#define WSTRIDE 132                // padded floats per (i,j) row in SMEM
#define SMEM_BYTES (IC * NJ * WSTRIDE * 4)   // 135168 B

// Scratch (static device arrays; no runtime allocation)
__device__ float g_logits[(size_t)B_TOT * IN_CAPS * NJ];   // 26.2 MB
__device__ float g_part[(size_t)NCHUNK * B_TOT * JM];      // 13.1 MB
__device__ float g_v[B_TOT * JM];                          // v between passes

typedef unsigned long long ull;

__device__ __forceinline__ ull pk2(float a, float b) {
    ull r; asm("mov.b64 %0, {%1, %2};" : "=l"(r) : "f"(a), "f"(b)); return r;
}
__device__ __forceinline__ void upk2(float& a, float& b, ull x) {
    asm("mov.b64 {%0, %1}, %2;" : "=f"(a), "=f"(b) : "l"(x));
}
// packed f32x2 fma: d = a*b + d  (2 fp32 FMAs per instruction)
__device__ __forceinline__ void fma2(ull& d, ull a, ull b) {
    asm("fma.rn.f32x2 %0, %1, %2, %0;" : "+l"(d) : "l"(a), "l"(b));
}
// packed f32x2 mul: d = a*b
__device__ __forceinline__ void mul2(ull& d, ull a, ull b) {
    asm("mul.rn.f32x2 %0, %1, %2;" : "=l"(d) : "l"(a), "l"(b));
}

// softmax over the 8 j-lanes (lane bits 1..3); logits are O(0.1) so no max-sub
__device__ __forceinline__ float softmax8(float logit) {
    float e = __expf(logit);
    float sm = e;
    sm += __shfl_xor_sync(0xffffffffu, sm, 2);
    sm += __shfl_xor_sync(0xffffffffu, sm, 4);
    sm += __shfl_xor_sync(0xffffffffu, sm, 8);
    return __fdividef(e, sm);
}

// Trivial warm-up so ncu (-s 5 -c 1) lands on routing_pass<2> at launch idx 5.
__global__ void warmup_probe() {
    if (threadIdx.x < JM) g_v[threadIdx.x] = 0.f;   // overwritten before first read
}

// Lane layout (m-split): mh = lane&1 (m-half), j = (lane>>1)&7, bsub = lane>>4.
// Each thread owns u/s/v for 8 m's -> 4 f32x2 pairs; ~70 live regs, no spills.
// MODE 0: uniform c = 1/8 — accumulate u directly into s, scale at end.
// MODE 1: a = u.v0; logits = a (stored); c = softmax_j(a).
// MODE 2: a = u.v1; logits = stored + a; c = softmax_j(logits).
template <int MODE>
__global__ void __launch_bounds__(512, 1) routing_pass(
    const float* __restrict__ x, const float* __restrict__ W)
{
    extern __shared__ float Ws[];   // [IC][NJ][WSTRIDE]
    const int chunk = blockIdx.x;
    const int bblk  = blockIdx.y;
    const int tid   = threadIdx.x;
    const int i0    = chunk * IC;

    // Stage W[i0:i0+IC] into SMEM (padded rows -> conflict-controlled access).
    {
        const float4* Wg = (const float4*)(W + (size_t)i0 * NJ * NN * NM);
        #pragma unroll 4
        for (int q = tid; q < IC * NJ * 32; q += 512) {
            float4 w = Wg[q];
            int ij = q >> 5, r = q & 31;
            *(float4*)&Ws[ij * WSTRIDE + r * 4] = w;
        }
    }
    __syncthreads();

    const int lane = tid & 31;
    const int warp = tid >> 5;
    const int mh   = lane & 1;            // m-half: m in [mh*8, mh*8+8)
    const int j    = (lane >> 1) & 7;
    const int bsub = lane >> 4;
    const int b    = bblk * BPC + warp * 2 + bsub;

    // v_prev for this (b, j, m-half), packed — 4 pairs in regs
    ull v2[4];
    if (MODE) {
        const float* vp = g_v + b * JM + j * NM + mh * 8;
        #pragma unroll
        for (int k = 0; k < 4; k++) v2[k] = pk2(vp[2 * k], vp[2 * k + 1]);
    }

    ull s2[4];
    #pragma unroll
    for (int k = 0; k < 4; k++) s2[k] = 0ull;

    const float* xbase = x + ((size_t)b * IN_CAPS + i0) * NN;
    float* lbase = g_logits + ((size_t)b * IN_CAPS + i0) * NJ + j;
    float4 xa = *(const float4*)(xbase);
    float4 xb = *(const float4*)(xbase + 4);

    #pragma unroll 2
    for (int il = 0; il < IC; il++) {
        float prevl = 0.f;
        if (MODE == 2) prevl = lbase[(size_t)il * NJ];   // early, hidden under FMAs

        // broadcast x_n into f32x2 pairs; prefetch next row
        ull x2[8];
        {
            float4 cxa = xa, cxb = xb;
            if (il + 1 < IC) {
                xa = *(const float4*)(xbase + (size_t)(il + 1) * NN);
                xb = *(const float4*)(xbase + (size_t)(il + 1) * NN + 4);
            }
            x2[0] = pk2(cxa.x, cxa.x); x2[1] = pk2(cxa.y, cxa.y);
            x2[2] = pk2(cxa.z, cxa.z); x2[3] = pk2(cxa.w, cxa.w);
            x2[4] = pk2(cxb.x, cxb.x); x2[5] = pk2(cxb.y, cxb.y);
            x2[6] = pk2(cxb.z, cxb.z); x2[7] = pk2(cxb.w, cxb.w);
        }

        const float* wp = &Ws[(il * NJ + j) * WSTRIDE + mh * 8];

        if (MODE == 0) {
            // accumulate u straight into s (c uniform)
            #pragma unroll
            for (int n = 0; n < 8; n++) {
                const ulonglong2* wv = (const ulonglong2*)(wp + n * 16);
                ulonglong2 wa = wv[0], wb = wv[1];
                fma2(s2[0], wa.x, x2[n]); fma2(s2[1], wa.y, x2[n]);
                fma2(s2[2], wb.x, x2[n]); fma2(s2[3], wb.y, x2[n]);
            }
        } else {
            // u for this (b, i, j, m-half): 32 packed FMAs (first n via mul)
            ull u2[4];
            {
                const ulonglong2* wv = (const ulonglong2*)(wp);
                ulonglong2 wa = wv[0], wb = wv[1];
                mul2(u2[0], wa.x, x2[0]); mul2(u2[1], wa.y, x2[0]);
                mul2(u2[2], wb.x, x2[0]); mul2(u2[3], wb.y, x2[0]);
            }
            #pragma unroll
            for (int n = 1; n < 8; n++) {
                const ulonglong2* wv = (const ulonglong2*)(wp + n * 16);
                ulonglong2 wa = wv[0], wb = wv[1];
                fma2(u2[0], wa.x, x2[n]); fma2(u2[1], wa.y, x2[n]);
                fma2(u2[2], wb.x, x2[n]); fma2(u2[3], wb.y, x2[n]);
            }

            // a = v . u  (4 pairs here, close over the other m-half via shfl 1)
            ull acc = 0ull;
            #pragma unroll
            for (int k = 0; k < 4; k++) fma2(acc, u2[k], v2[k]);
            float al, ah; upk2(al, ah, acc);
            float ap = al + ah;
            float a = ap + __shfl_xor_sync(0xffffffffu, ap, 1);

            float logit = (MODE == 1) ? a : (prevl + a);
            if (MODE == 1 && mh == 0) lbase[(size_t)il * NJ] = a;
            float c = softmax8(logit);
            ull c2 = pk2(c, c);
            #pragma unroll
            for (int k = 0; k < 4; k++) fma2(s2[k], u2[k], c2);
        }
    }

    if (MODE == 0) {
        #pragma unroll
        for (int k = 0; k < 4; k++) {
            float lo, hi; upk2(lo, hi, s2[k]);
            s2[k] = pk2(lo * 0.125f, hi * 0.125f);
        }
    }

    // write s-partials for this chunk (two float4 stores)
    float* pp = g_part + ((size_t)chunk * B_TOT + b) * JM + j * NM + mh * 8;
    {
        float a0, a1, a2, a3;
        upk2(a0, a1, s2[0]); upk2(a2, a3, s2[1]);
        *(float4*)pp = make_float4(a0, a1, a2, a3);
        upk2(a0, a1, s2[2]); upk2(a2, a3, s2[3]);
        *(float4*)(pp + 4) = make_float4(a0, a1, a2, a3);
    }
}

// Sum partials over chunks (4 parallel groups of 25, deterministic), squash, write v.
__global__ void __launch_bounds__(512) reduce_squash(float* __restrict__ vout)
{
    const int b = blockIdx.x, t = threadIdx.x;
    const int g = t >> 7, w = t & 127;        // group 0..3, element 0..127
    __shared__ float sh[4][JM];

    const float* p = g_part + ((size_t)(g * 25) * B_TOT + b) * JM + w;
    float a0 = 0.f, a1 = 0.f, a2 = 0.f, a3 = 0.f;
    #pragma unroll
    for (int k = 0; k < 24; k += 4) {
        a0 += p[(size_t)(k + 0) * B_TOT * JM];
        a1 += p[(size_t)(k + 1) * B_TOT * JM];
        a2 += p[(size_t)(k + 2) * B_TOT * JM];
        a3 += p[(size_t)(k + 3) * B_TOT * JM];
    }
    a0 += p[(size_t)24 * B_TOT * JM];
    sh[g][w] = (a0 + a1) + (a2 + a3);
    __syncthreads();

    if (t < JM) {
        float tot = ((sh[0][t] + sh[1][t]) + (sh[2][t] + sh[3][t]));
        const int j = t >> 4;
        float sq = 0.f;
        #pragma unroll
        for (int m = 0; m < NM; m++) {
            int e = j * NM + m;
            float z = ((sh[0][e] + sh[1][e]) + (sh[2][e] + sh[3][e]));
            sq += z * z;
        }
        float f = sq / ((1.0f + sq) * sqrtf(sq));
        vout[b * JM + t] = tot * f;
    }
}

extern "C" void kernel_launch(void* const* d_in, const int* in_sizes, int n_in,
                              void* d_out, int out_size)
{
    const float* x = (const float*)d_in[0];
    const float* W = (const float*)d_in[1];
    // defensive: identify by element count (x: 6,553,600; W: 3,276,800)
    if (n_in >= 2 && in_sizes[0] == IN_CAPS * NJ * NN * NM) {
        W = (const float*)d_in[0];
        x = (const float*)d_in[1];
    }

    cudaFuncSetAttribute(routing_pass<0>, cudaFuncAttributeMaxDynamicSharedMemorySize, SMEM_BYTES);
    cudaFuncSetAttribute(routing_pass<1>, cudaFuncAttributeMaxDynamicSharedMemorySize, SMEM_BYTES);
    cudaFuncSetAttribute(routing_pass<2>, cudaFuncAttributeMaxDynamicSharedMemorySize, SMEM_BYTES);

    float* vbuf = nullptr;
    cudaGetSymbolAddress((void**)&vbuf, g_v);

    dim3 grid(NCHUNK, NBB);

    // launch 0: probe so ncu (-s 5) captures routing_pass<2> at index 5
    warmup_probe<<<1, 128>>>();
    // iteration 0: c uniform -> s0 -> v0
    routing_pass<0><<<grid, 512, SMEM_BYTES>>>(x, W);
    reduce_squash<<<B_TOT, 512>>>(vbuf);
    // iteration 1: logits = a(v0); c = softmax -> s1 -> v1
    routing_pass<1><<<grid, 512, SMEM_BYTES>>>(x, W);
    reduce_squash<<<B_TOT, 512>>>(vbuf);
    // final: logits += a(v1); c = softmax -> s2 -> v2 = output
    routing_pass<2><<<grid, 512, SMEM_BYTES>>>(x, W);
    reduce_squash<<<B_TOT, 512>>>((float*)d_out);
}

// round 6
// speedup vs baseline: 2.8104x; 2.8104x over previous
#include <cuda_runtime.h>
#include <cstdint>

// Problem constants
#define B_TOT   256
#define IN_CAPS 3200
#define NJ      8
#define NM      16
#define NN      8
#define JM      (NJ * NM)          // 128

// Tiling
#define IC      32                 // input caps per chunk
#define NCHUNK  (IN_CAPS / IC)     // 100
#define BPC     64                 // batch elems per CTA (16 warps x 4 reg-b)
#define NBB     (B_TOT / BPC)      // 4
#define WSTRIDE 132                // padded floats per (i,j) row in SMEM
#define SMEM_BYTES (IC * NJ * WSTRIDE * 4)   // 135168 B

// Scratch (static device arrays; no runtime allocation)
__device__ float g_logits[(size_t)B_TOT * IN_CAPS * NJ];   // 26.2 MB
__device__ float g_part[(size_t)NCHUNK * B_TOT * JM];      // 13.1 MB
__device__ float g_v[B_TOT * JM];                          // v between passes

typedef unsigned long long ull;

__device__ __forceinline__ ull pk2(float a, float b) {
    ull r; asm("mov.b64 %0, {%1, %2};" : "=l"(r) : "f"(a), "f"(b)); return r;
}
__device__ __forceinline__ void upk2(float& a, float& b, ull x) {
    asm("mov.b64 {%0, %1}, %2;" : "=f"(a), "=f"(b) : "l"(x));
}
// packed f32x2 fma: d = a*b + d
__device__ __forceinline__ void fma2(ull& d, ull a, ull b) {
    asm("fma.rn.f32x2 %0, %1, %2, %0;" : "+l"(d) : "l"(a), "l"(b));
}
// packed f32x2 mul: d = a*b
__device__ __forceinline__ void mul2(ull& d, ull a, ull b) {
    asm("mul.rn.f32x2 %0, %1, %2;" : "=l"(d) : "l"(a), "l"(b));
}

// Trivial warm-up so ncu (-s 5 -c 1) lands on routing_pass<2> at launch idx 5.
__global__ void warmup_probe() {
    if (threadIdx.x < JM) g_v[threadIdx.x] = 0.f;   // overwritten before first read
}

// Lane layout: lane = mq*8 + j  (mq = m-quarter 0..3, j = out-cap 0..7).
// Every lane reads a DISTINCT 16B W segment per LDS.128 (no broadcast waste;
// (j+mq)*16B mod 128 tiles banks in 4 conflict-free phases with WSTRIDE=132).
// Each lane carries 4 batch elems (warp-uniform) in registers:
//   u/s/v packed along m: pair k of b = (val[m0+2k], val[m0+2k+1]), m0 = mq*4.
// Dot over m closes via shfl 8,16 (mq); softmax over j via shfl 1,2,4.
// MODE 0: uniform c = 1/8 — accumulate u into s directly, scale at end.
// MODE 1: a = u.v0; logits = a (stored); c = softmax_j(a).
// MODE 2: a = u.v1; logits = stored + a; c = softmax_j(logits).
template <int MODE>
__global__ void __launch_bounds__(512, 1) routing_pass(
    const float* __restrict__ x, const float* __restrict__ W)
{
    extern __shared__ float Ws[];   // [IC][NJ][WSTRIDE]
    const int chunk = blockIdx.x;
    const int bblk  = blockIdx.y;
    const int tid   = threadIdx.x;
    const int i0    = chunk * IC;

    // Stage W[i0:i0+IC] into SMEM (padded rows).
    {
        const float4* Wg = (const float4*)(W + (size_t)i0 * NJ * NN * NM);
        #pragma unroll 4
        for (int q = tid; q < IC * NJ * 32; q += 512) {
            float4 w = Wg[q];
            int ij = q >> 5, r = q & 31;
            *(float4*)&Ws[ij * WSTRIDE + r * 4] = w;
        }
    }
    __syncthreads();

    const int lane = tid & 31;
    const int warp = tid >> 5;
    const int mq   = lane >> 3;           // m-quarter
    const int j    = lane & 7;
    const int bbase = bblk * BPC + warp * 4;

    // v for the 4 b's (MODE>0): 2 pairs each, m-packed
    ull v2[4][2];
    if (MODE) {
        #pragma unroll
        for (int b = 0; b < 4; b++) {
            float4 vv = *(const float4*)(g_v + (size_t)(bbase + b) * JM + j * NM + mq * 4);
            v2[b][0] = pk2(vv.x, vv.y);
            v2[b][1] = pk2(vv.z, vv.w);
        }
    }

    ull s2[4][2];
    #pragma unroll
    for (int b = 0; b < 4; b++) { s2[b][0] = 0ull; s2[b][1] = 0ull; }

    // single base pointers; per-b offsets are compile-time immediates
    const float* xbase = x + ((size_t)bbase * IN_CAPS + i0) * NN;
    float* lbase = g_logits + ((size_t)bbase * IN_CAPS + i0) * NJ + j;

    #pragma unroll 1
    for (int il = 0; il < IC; il++) {
        // x for 4 b's: 8 warp-uniform LDG.128 (L1 dedups same-address lanes)
        float xv[4][8];
        #pragma unroll
        for (int b = 0; b < 4; b++) {
            const float* xp = xbase + (size_t)b * IN_CAPS * NN + il * NN;
            float4 A = *(const float4*)xp;
            float4 Bq = *(const float4*)(xp + 4);
            xv[b][0] = A.x;  xv[b][1] = A.y;  xv[b][2] = A.z;  xv[b][3] = A.w;
            xv[b][4] = Bq.x; xv[b][5] = Bq.y; xv[b][6] = Bq.z; xv[b][7] = Bq.w;
        }
        float pl[4];
        if (MODE == 2) {
            #pragma unroll
            for (int b = 0; b < 4; b++)
                pl[b] = lbase[(size_t)b * IN_CAPS * NJ + il * NJ];
        }

        // W slice for this lane: 4 m's (mq*4..+4) of row (il, j), all 8 n
        const float* wp = &Ws[(il * NJ + j) * WSTRIDE + mq * 4];

        if (MODE == 0) {
            #pragma unroll
            for (int n = 0; n < 8; n++) {
                ulonglong2 wv = *(const ulonglong2*)(wp + n * NM);
                #pragma unroll
                for (int b = 0; b < 4; b++) {
                    ull xd = pk2(xv[b][n], xv[b][n]);
                    fma2(s2[b][0], wv.x, xd);
                    fma2(s2[b][1], wv.y, xd);
                }
            }
        } else {
            ull u2[4][2];
            {   // n = 0 via mul (saves zero-init)
                ulonglong2 wv = *(const ulonglong2*)(wp);
                #pragma unroll
                for (int b = 0; b < 4; b++) {
                    ull xd = pk2(xv[b][0], xv[b][0]);
                    mul2(u2[b][0], wv.x, xd);
                    mul2(u2[b][1], wv.y, xd);
                }
            }
            #pragma unroll
            for (int n = 1; n < 8; n++) {
                ulonglong2 wv = *(const ulonglong2*)(wp + n * NM);
                #pragma unroll
                for (int b = 0; b < 4; b++) {
                    ull xd = pk2(xv[b][n], xv[b][n]);
                    fma2(u2[b][0], wv.x, xd);
                    fma2(u2[b][1], wv.y, xd);
                }
            }

            // a[b] = v . u over this lane's 4 m, then close over mq lanes
            float a[4];
            #pragma unroll
            for (int b = 0; b < 4; b++) {
                ull acc = 0ull;
                fma2(acc, u2[b][0], v2[b][0]);
                fma2(acc, u2[b][1], v2[b][1]);
                float lo, hi; upk2(lo, hi, acc);
                a[b] = lo + hi;
            }
            #pragma unroll
            for (int b = 0; b < 4; b++) {
                a[b] += __shfl_xor_sync(0xffffffffu, a[b], 8);
                a[b] += __shfl_xor_sync(0xffffffffu, a[b], 16);
            }

            // softmax over j (logits are O(0.1): no max-sub needed)
            #pragma unroll
            for (int b = 0; b < 4; b++) {
                float logit;
                if (MODE == 1) {
                    if (mq == 0) lbase[(size_t)b * IN_CAPS * NJ + il * NJ] = a[b];
                    logit = a[b];
                } else {
                    logit = a[b] + pl[b];
                }
                float e = __expf(logit);
                float sm = e;
                sm += __shfl_xor_sync(0xffffffffu, sm, 1);
                sm += __shfl_xor_sync(0xffffffffu, sm, 2);
                sm += __shfl_xor_sync(0xffffffffu, sm, 4);
                float c = __fdividef(e, sm);
                ull cd = pk2(c, c);
                fma2(s2[b][0], u2[b][0], cd);
                fma2(s2[b][1], u2[b][1], cd);
            }
        }
    }

    if (MODE == 0) {
        #pragma unroll
        for (int b = 0; b < 4; b++) {
            float lo, hi;
            upk2(lo, hi, s2[b][0]); s2[b][0] = pk2(lo * 0.125f, hi * 0.125f);
            upk2(lo, hi, s2[b][1]); s2[b][1] = pk2(lo * 0.125f, hi * 0.125f);
        }
    }

    // write s-partials: one float4 per (lane, b); warp covers 512B/b, no overlap
    #pragma unroll
    for (int b = 0; b < 4; b++) {
        float a0, a1, a2, a3;
        upk2(a0, a1, s2[b][0]); upk2(a2, a3, s2[b][1]);
        float* pp = g_part + ((size_t)chunk * B_TOT + bbase + b) * JM + j * NM + mq * 4;
        *(float4*)pp = make_float4(a0, a1, a2, a3);
    }
}

// Sum partials over chunks (4 parallel groups of 25, deterministic), squash, write v.
__global__ void __launch_bounds__(512) reduce_squash(float* __restrict__ vout)
{
    const int b = blockIdx.x, t = threadIdx.x;
    const int g = t >> 7, w = t & 127;        // group 0..3, element 0..127
    __shared__ float sh[4][JM];

    const float* p = g_part + ((size_t)(g * 25) * B_TOT + b) * JM + w;
    float a0 = 0.f, a1 = 0.f, a2 = 0.f, a3 = 0.f;
    #pragma unroll
    for (int k = 0; k < 24; k += 4) {
        a0 += p[(size_t)(k + 0) * B_TOT * JM];
        a1 += p[(size_t)(k + 1) * B_TOT * JM];
        a2 += p[(size_t)(k + 2) * B_TOT * JM];
        a3 += p[(size_t)(k + 3) * B_TOT * JM];
    }
    a0 += p[(size_t)24 * B_TOT * JM];
    sh[g][w] = (a0 + a1) + (a2 + a3);
    __syncthreads();

    if (t < JM) {
        float tot = ((sh[0][t] + sh[1][t]) + (sh[2][t] + sh[3][t]));
        const int j = t >> 4;
        float sq = 0.f;
        #pragma unroll
        for (int m = 0; m < NM; m++) {
            int e = j * NM + m;
            float z = ((sh[0][e] + sh[1][e]) + (sh[2][e] + sh[3][e]));
            sq += z * z;
        }
        float f = sq / ((1.0f + sq) * sqrtf(sq));
        vout[b * JM + t] = tot * f;
    }
}

extern "C" void kernel_launch(void* const* d_in, const int* in_sizes, int n_in,
                              void* d_out, int out_size)
{
    const float* x = (const float*)d_in[0];
    const float* W = (const float*)d_in[1];
    // defensive: identify by element count (x: 6,553,600; W: 3,276,800)
    if (n_in >= 2 && in_sizes[0] == IN_CAPS * NJ * NN * NM) {
        W = (const float*)d_in[0];
        x = (const float*)d_in[1];
    }

    cudaFuncSetAttribute(routing_pass<0>, cudaFuncAttributeMaxDynamicSharedMemorySize, SMEM_BYTES);
    cudaFuncSetAttribute(routing_pass<1>, cudaFuncAttributeMaxDynamicSharedMemorySize, SMEM_BYTES);
    cudaFuncSetAttribute(routing_pass<2>, cudaFuncAttributeMaxDynamicSharedMemorySize, SMEM_BYTES);

    float* vbuf = nullptr;
    cudaGetSymbolAddress((void**)&vbuf, g_v);

    dim3 grid(NCHUNK, NBB);

    // launch 0: probe so ncu (-s 5) captures routing_pass<2> at index 5
    warmup_probe<<<1, 128>>>();
    // iteration 0: c uniform -> s0 -> v0
    routing_pass<0><<<grid, 512, SMEM_BYTES>>>(x, W);
    reduce_squash<<<B_TOT, 512>>>(vbuf);
    // iteration 1: logits = a(v0); c = softmax -> s1 -> v1
    routing_pass<1><<<grid, 512, SMEM_BYTES>>>(x, W);
    reduce_squash<<<B_TOT, 512>>>(vbuf);
    // final: logits += a(v1); c = softmax -> s2 -> v2 = output
    routing_pass<2><<<grid, 512, SMEM_BYTES>>>(x, W);
    reduce_squash<<<B_TOT, 512>>>((float*)d_out);
}

// round 9
// speedup vs baseline: 3.0888x; 1.0991x over previous
#include <cuda_runtime.h>
#include <cstdint>

// Problem constants
#define B_TOT   256
#define IN_CAPS 3200
#define NJ      8
#define NM      16
#define NN      8
#define JM      (NJ * NM)          // 128

// Tiling
#define IC      32                 // input caps per chunk
#define NCHUNK  (IN_CAPS / IC)     // 100
#define BPC     64                 // batch elems per CTA (16 warps x 4 reg-b)
#define NBB     (B_TOT / BPC)      // 4
#define WSTRIDE 132                // padded floats per (i,j) row in SMEM
#define XS_FLOATS (BPC * IC * NN)  // 16384 floats = 64KB x tile
#define SMEM_BYTES (XS_FLOATS * 4 + IC * NJ * WSTRIDE * 4)   // 65536 + 135168 = 200704 B

// Scratch (static device arrays; no runtime allocation)
// logits packed [bgroup(64)][i(3200)][j(8)][b4(4)] for 1-wavefront store/load
__device__ float g_logits[(size_t)(B_TOT / 4) * IN_CAPS * NJ * 4];   // 26.2 MB
__device__ float g_part[(size_t)NCHUNK * B_TOT * JM];                // 13.1 MB
__device__ float g_v[B_TOT * JM];                                    // v between passes

typedef unsigned long long ull;

__device__ __forceinline__ ull pk2(float a, float b) {
    ull r; asm("mov.b64 %0, {%1, %2};" : "=l"(r) : "f"(a), "f"(b)); return r;
}
__device__ __forceinline__ void upk2(float& a, float& b, ull x) {
    asm("mov.b64 {%0, %1}, %2;" : "=f"(a), "=f"(b) : "l"(x));
}
// packed f32x2 fma: d = a*b + d
__device__ __forceinline__ void fma2(ull& d, ull a, ull b) {
    asm("fma.rn.f32x2 %0, %1, %2, %0;" : "+l"(d) : "l"(a), "l"(b));
}
// packed f32x2 mul: d = a*b
__device__ __forceinline__ void mul2(ull& d, ull a, ull b) {
    asm("mul.rn.f32x2 %0, %1, %2;" : "=l"(d) : "l"(a), "l"(b));
}

// Trivial warm-up so ncu (-s 5 -c 1) lands on routing_pass<2> at launch idx 5.
__global__ void warmup_probe() {
    if (threadIdx.x < JM) g_v[threadIdx.x] = 0.f;   // overwritten before first read
}

// Lane layout: lane = mq*8 + j (mq = m-quarter, j = out-cap). Per LDS.128 on W
// every lane reads a DISTINCT 16B segment (conflict-free with WSTRIDE=132).
// Each lane carries 4 batch elems; u/s/v m-packed as f32x2 (pairs (m0,m0+1)).
// Dot closes over mq via shfl.xor 8,16; softmax sums over j via shfl.xor 1,2,4.
// x is staged in SMEM (broadcast LDS, lat ~29, replaces per-il LDG lat ~234).
// MODE 0: uniform c = 1/8 — accumulate u into s directly, scale at end.
// MODE 1: a = u.v0; logits = a (stored packed); c = softmax_j(a).
// MODE 2: a = u.v1; logits = stored + a; c = softmax_j(logits).
template <int MODE>
__global__ void __launch_bounds__(512, 1) routing_pass(
    const float* __restrict__ x, const float* __restrict__ W)
{
    extern __shared__ float smem_f[];
    float* Xs = smem_f;                  // [BPC][IC][NN]  (CTA-local batch idx)
    float* Ws = smem_f + XS_FLOATS;      // [IC][NJ][WSTRIDE]

    const int chunk = blockIdx.x;
    const int bblk  = blockIdx.y;
    const int tid   = threadIdx.x;
    const int i0    = chunk * IC;

    // Stage W[i0:i0+IC] into SMEM (padded rows).
    {
        const float4* Wg = (const float4*)(W + (size_t)i0 * NJ * NN * NM);
        #pragma unroll 4
        for (int q = tid; q < IC * NJ * 32; q += 512) {
            float4 w = Wg[q];
            int ij = q >> 5, r = q & 31;
            *(float4*)&Ws[ij * WSTRIDE + r * 4] = w;
        }
    }
    // Stage x tile [BPC][IC][NN] into SMEM (coalesced; 8 float4 per thread).
    {
        #pragma unroll
        for (int q = tid; q < BPC * IC * 2; q += 512) {
            int b = q >> 6;              // 64 float4 per batch elem
            int r = q & 63;
            *(float4*)&Xs[b * (IC * NN) + r * 4] =
                *(const float4*)(x + ((size_t)(bblk * BPC + b) * IN_CAPS + i0) * NN + r * 4);
        }
    }
    __syncthreads();

    const int lane = tid & 31;
    const int warp = tid >> 5;
    const int mq   = lane >> 3;           // m-quarter
    const int j    = lane & 7;
    const int bbase = bblk * BPC + warp * 4;
    const int bgroup = bbase >> 2;        // logits group (one per warp)

    // v for the 4 b's (MODE>0): 2 pairs each, m-packed
    ull v2[4][2];
    if (MODE) {
        #pragma unroll
        for (int b = 0; b < 4; b++) {
            float4 vv = *(const float4*)(g_v + (size_t)(bbase + b) * JM + j * NM + mq * 4);
            v2[b][0] = pk2(vv.x, vv.y);
            v2[b][1] = pk2(vv.z, vv.w);
        }
    }

    ull s2[4][2];
    #pragma unroll
    for (int b = 0; b < 4; b++) { s2[b][0] = 0ull; s2[b][1] = 0ull; }

    float* lrow = g_logits + ((size_t)bgroup * IN_CAPS + i0) * 32 + j * 4;
    // this warp's slice of the x tile (CTA-local batch base = warp*4)
    const float* xwarp = Xs + (size_t)(warp * 4) * (IC * NN);

    #pragma unroll 1
    for (int il = 0; il < IC; il++) {
        // prev logits for the 4 b's: one LDG.128 (dup across mq lanes),
        // issued at loop top and consumed ~100 instructions later
        float4 pl4;
        if (MODE == 2) pl4 = *(const float4*)(lrow + (size_t)il * 32);

        // W[il] slice for this lane: 8 LDS.128 -> 16 f32x2 pairs in regs
        const float* wp = &Ws[(il * NJ + j) * WSTRIDE + mq * 4];
        ull wr[8][2];
        #pragma unroll
        for (int n = 0; n < 8; n++) {
            ulonglong2 wv = *(const ulonglong2*)(wp + n * NM);
            wr[n][0] = wv.x; wr[n][1] = wv.y;
        }

        float a4[4];
        #pragma unroll
        for (int b = 0; b < 4; b++) {
            // x[warp*4 + b, il, :] from SMEM: 2 broadcast LDS.128
            const float4* xp = (const float4*)&xwarp[((size_t)b * IC + il) * NN];
            float4 A = xp[0], Bq = xp[1];

            ull xd, u0, u1;
            xd = pk2(A.x, A.x);  mul2(u0, wr[0][0], xd); mul2(u1, wr[0][1], xd);
            xd = pk2(A.y, A.y);  fma2(u0, wr[1][0], xd); fma2(u1, wr[1][1], xd);
            xd = pk2(A.z, A.z);  fma2(u0, wr[2][0], xd); fma2(u1, wr[2][1], xd);
            xd = pk2(A.w, A.w);  fma2(u0, wr[3][0], xd); fma2(u1, wr[3][1], xd);
            xd = pk2(Bq.x, Bq.x); fma2(u0, wr[4][0], xd); fma2(u1, wr[4][1], xd);
            xd = pk2(Bq.y, Bq.y); fma2(u0, wr[5][0], xd); fma2(u1, wr[5][1], xd);
            xd = pk2(Bq.z, Bq.z); fma2(u0, wr[6][0], xd); fma2(u1, wr[6][1], xd);
            xd = pk2(Bq.w, Bq.w); fma2(u0, wr[7][0], xd); fma2(u1, wr[7][1], xd);

            if (MODE == 0) {
                // c uniform: accumulate u into s directly
                ull one = pk2(1.f, 1.f);
                fma2(s2[b][0], u0, one);
                fma2(s2[b][1], u1, one);
            } else {
                // a = v.u over this lane's 4 m, closed over mq lanes via shfl
                ull acc = 0ull;
                fma2(acc, u0, v2[b][0]);
                fma2(acc, u1, v2[b][1]);
                float lo, hi; upk2(lo, hi, acc);
                float a = lo + hi;
                a += __shfl_xor_sync(0xffffffffu, a, 8);
                a += __shfl_xor_sync(0xffffffffu, a, 16);
                a4[b] = a;

                float logit = a;
                if (MODE == 2) {
                    logit += (b == 0) ? pl4.x : (b == 1) ? pl4.y
                           : (b == 2) ? pl4.z : pl4.w;
                }
                // softmax over j lanes (logits O(0.1): no max-sub needed)
                float e = __expf(logit);
                float sm = e;
                sm += __shfl_xor_sync(0xffffffffu, sm, 1);
                sm += __shfl_xor_sync(0xffffffffu, sm, 2);
                sm += __shfl_xor_sync(0xffffffffu, sm, 4);
                float c = __fdividef(e, sm);
                ull cd = pk2(c, c);
                fma2(s2[b][0], u0, cd);
                fma2(s2[b][1], u1, cd);
            }
        }

        if (MODE == 1 && mq == 0)
            *(float4*)(lrow + (size_t)il * 32) = make_float4(a4[0], a4[1], a4[2], a4[3]);
    }

    if (MODE == 0) {
        #pragma unroll
        for (int b = 0; b < 4; b++) {
            float lo, hi;
            upk2(lo, hi, s2[b][0]); s2[b][0] = pk2(lo * 0.125f, hi * 0.125f);
            upk2(lo, hi, s2[b][1]); s2[b][1] = pk2(lo * 0.125f, hi * 0.125f);
        }
    }

    // write s-partials: one float4 per (lane, b)
    #pragma unroll
    for (int b = 0; b < 4; b++) {
        float a0, a1, a2, a3;
        upk2(a0, a1, s2[b][0]); upk2(a2, a3, s2[b][1]);
        float* pp = g_part + ((size_t)chunk * B_TOT + bbase + b) * JM + j * NM + mq * 4;
        *(float4*)pp = make_float4(a0, a1, a2, a3);
    }
}

// Sum partials over chunks (4 parallel groups of 25, deterministic), squash, write v.
__global__ void __launch_bounds__(512) reduce_squash(float* __restrict__ vout)
{
    const int b = blockIdx.x, t = threadIdx.x;
    const int g = t >> 7, w = t & 127;        // group 0..3, element 0..127
    __shared__ float sh[4][JM];

    const float* p = g_part + ((size_t)(g * 25) * B_TOT + b) * JM + w;
    float a0 = 0.f, a1 = 0.f, a2 = 0.f, a3 = 0.f;
    #pragma unroll
    for (int k = 0; k < 24; k += 4) {
        a0 += p[(size_t)(k + 0) * B_TOT * JM];
        a1 += p[(size_t)(k + 1) * B_TOT * JM];
        a2 += p[(size_t)(k + 2) * B_TOT * JM];
        a3 += p[(size_t)(k + 3) * B_TOT * JM];
    }
    a0 += p[(size_t)24 * B_TOT * JM];
    sh[g][w] = (a0 + a1) + (a2 + a3);
    __syncthreads();

    if (t < JM) {
        float tot = ((sh[0][t] + sh[1][t]) + (sh[2][t] + sh[3][t]));
        const int j = t >> 4;
        float sq = 0.f;
        #pragma unroll
        for (int m = 0; m < NM; m++) {
            int e = j * NM + m;
            float z = ((sh[0][e] + sh[1][e]) + (sh[2][e] + sh[3][e]));
            sq += z * z;
        }
        float f = sq / ((1.0f + sq) * sqrtf(sq));
        vout[b * JM + t] = tot * f;
    }
}

extern "C" void kernel_launch(void* const* d_in, const int* in_sizes, int n_in,
                              void* d_out, int out_size)
{
    const float* x = (const float*)d_in[0];
    const float* W = (const float*)d_in[1];
    // defensive: identify by element count (x: 6,553,600; W: 3,276,800)
    if (n_in >= 2 && in_sizes[0] == IN_CAPS * NJ * NN * NM) {
        W = (const float*)d_in[0];
        x = (const float*)d_in[1];
    }

    cudaFuncSetAttribute(routing_pass<0>, cudaFuncAttributeMaxDynamicSharedMemorySize, SMEM_BYTES);
    cudaFuncSetAttribute(routing_pass<1>, cudaFuncAttributeMaxDynamicSharedMemorySize, SMEM_BYTES);
    cudaFuncSetAttribute(routing_pass<2>, cudaFuncAttributeMaxDynamicSharedMemorySize, SMEM_BYTES);

    float* vbuf = nullptr;
    cudaGetSymbolAddress((void**)&vbuf, g_v);

    dim3 grid(NCHUNK, NBB);

    // launch 0: probe so ncu (-s 5) captures routing_pass<2> at index 5
    warmup_probe<<<1, 128>>>();
    // iteration 0: c uniform -> s0 -> v0
    routing_pass<0><<<grid, 512, SMEM_BYTES>>>(x, W);
    reduce_squash<<<B_TOT, 512>>>(vbuf);
    // iteration 1: logits = a(v0); c = softmax -> s1 -> v1
    routing_pass<1><<<grid, 512, SMEM_BYTES>>>(x, W);
    reduce_squash<<<B_TOT, 512>>>(vbuf);
    // final: logits += a(v1); c = softmax -> s2 -> v2 = output
    routing_pass<2><<<grid, 512, SMEM_BYTES>>>(x, W);
    reduce_squash<<<B_TOT, 512>>>((float*)d_out);
}